// round 2
// baseline (speedup 1.0000x reference)
#include <cuda_runtime.h>
#include <cstddef>

#define KC 16
#define NMAX 100000
#define E2MAX 3200000
#define BP_EPS 1e-12f

// Persistent scratch (device globals; no allocation allowed).
static __device__ float g_lm[(size_t)E2MAX * KC];   // log2(messages), 204.8 MB
static __device__ float g_SA[(size_t)NMAX * KC];    // node accumulators (ping)
static __device__ float g_SB[(size_t)NMAX * KC];    // node accumulators (pong)
static __device__ float g_psi[KC * KC];
static __device__ float g_acoef[KC];
static __device__ float g_off;
static __device__ int   g_fast;

__device__ __forceinline__ float ex2f(float x) {
    float y; asm("ex2.approx.f32 %0, %1;" : "=f"(y) : "f"(x)); return y;
}
__device__ __forceinline__ float lg2f_(float x) {
    float y; asm("lg2.approx.f32 %0, %1;" : "=f"(y) : "f"(x)); return y;
}
__device__ __forceinline__ void red_v4(float* p, float a, float b, float c, float d) {
    asm volatile("red.global.add.v4.f32 [%0], {%1, %2, %3, %4};"
                 :: "l"(p), "f"(a), "f"(b), "f"(c), "f"(d) : "memory");
}

// psi = exp(log_psi); detect diag-plus-constant structure for the fast path.
__global__ void prep_psi_kernel(const float* __restrict__ logpsi) {
    __shared__ float psi[KC * KC];
    int t = threadIdx.x;
    if (t < KC * KC) { float p = expf(logpsi[t]); psi[t] = p; g_psi[t] = p; }
    __syncthreads();
    if (t == 0) {
        float off = psi[1];
        int fast = 1;
        for (int i = 0; i < KC; i++)
            for (int j = 0; j < KC; j++)
                if (i != j && psi[i * KC + j] != off) fast = 0;
        g_fast = fast;
        g_off = off;
        for (int c = 0; c < KC; c++) g_acoef[c] = psi[c * KC + c] - off;
    }
}

// S[which] := log2(prior)
__global__ void init_S_kernel(const float* __restrict__ prior, int which, int n16) {
    int i = blockIdx.x * blockDim.x + threadIdx.x;
    float* S = which ? g_SB : g_SA;
    if (i < n16) S[i] = log2f(prior[i]);
}

// Inject initial uniform messages: S[dst[e]][:] += log2(1/16) = -4 exactly.
__global__ void acc_uniform_kernel(const int* __restrict__ dst, int which, int e2) {
    int e = blockIdx.x * blockDim.x + threadIdx.x;
    if (e >= e2) return;
    float* S = which ? g_SB : g_SA;
    float* p = S + (size_t)dst[e] * KC;
    red_v4(p + 0,  -4.f, -4.f, -4.f, -4.f);
    red_v4(p + 4,  -4.f, -4.f, -4.f, -4.f);
    red_v4(p + 8,  -4.f, -4.f, -4.f, -4.f);
    red_v4(p + 12, -4.f, -4.f, -4.f, -4.f);
}

// One message update: b = max(2^(Sin_row - lmrev), EPS); m = b @ psi; write
// log2(m / sum(m)) to out_row and red-add it into red_row (next iter's S).
__device__ __forceinline__ void do_msg(
    const float* __restrict__ Sin_row, const float lmrev[KC],
    float* __restrict__ out_row, float* __restrict__ red_row,
    int fast, float off, const float* __restrict__ s_a, const float* __restrict__ s_psi)
{
    float P[KC];
    const float4* pp = reinterpret_cast<const float4*>(Sin_row);
    #pragma unroll
    for (int q = 0; q < 4; q++) {
        float4 v = pp[q];
        P[4*q+0] = v.x; P[4*q+1] = v.y; P[4*q+2] = v.z; P[4*q+3] = v.w;
    }
    float b[KC];
    float T = 0.f;
    #pragma unroll
    for (int c = 0; c < KC; c++) {
        float x = ex2f(P[c] - lmrev[c]);
        x = fmaxf(x, BP_EPS);
        b[c] = x;
        T += x;
    }
    float m[KC];
    float Z = 0.f;
    if (fast) {
        float oT = off * T;
        #pragma unroll
        for (int c = 0; c < KC; c++) {
            float v = fmaf(s_a[c], b[c], oT);
            m[c] = v; Z += v;
        }
    } else {
        #pragma unroll
        for (int c = 0; c < KC; c++) {
            float acc = 0.f;
            #pragma unroll
            for (int j = 0; j < KC; j++) acc = fmaf(b[j], s_psi[j * KC + c], acc);
            m[c] = acc; Z += acc;
        }
    }
    float lZ = lg2f_(Z);
    #pragma unroll
    for (int c = 0; c < KC; c++) m[c] = lg2f_(m[c]) - lZ;

    float4* po = reinterpret_cast<float4*>(out_row);
    #pragma unroll
    for (int q = 0; q < 4; q++) {
        float4 v;
        v.x = m[4*q+0]; v.y = m[4*q+1]; v.z = m[4*q+2]; v.w = m[4*q+3];
        po[q] = v;
    }
    red_v4(red_row + 0,  m[0],  m[1],  m[2],  m[3]);
    red_v4(red_row + 4,  m[4],  m[5],  m[6],  m[7]);
    red_v4(red_row + 8,  m[8],  m[9],  m[10], m[11]);
    red_v4(red_row + 12, m[12], m[13], m[14], m[15]);
}

// One BP iteration over edge pairs: updates g_lm in place (each pair owns its
// two rows) and accumulates next-iteration S (pre-initialized to log2 prior).
// ab==1: Sin = g_SA, Snext = g_SB.  ab==0: Sin = g_SB, Snext = g_SA.
__global__ void __launch_bounds__(256) update_kernel(
    const int* __restrict__ src, const int* __restrict__ dst, const int* __restrict__ rev,
    int ab, int E, int first)
{
    __shared__ float s_psi[KC * KC];
    __shared__ float s_a[KC];
    __shared__ float s_off;
    __shared__ int   s_fast;
    int t = threadIdx.x;
    if (t < KC * KC) s_psi[t] = g_psi[t];
    if (t < KC) s_a[t] = g_acoef[t];
    if (t == 0) { s_off = g_off; s_fast = g_fast; }
    __syncthreads();

    const float* Sin  = ab ? g_SA : g_SB;
    float*       Snext = ab ? g_SB : g_SA;

    int i = blockIdx.x * blockDim.x + t;
    if (i >= E) return;

    int s = src[i], d = dst[i], er = rev[i];
    const int fast = s_fast;
    const float off = s_off;

    float lmf[KC], lmr[KC];
    if (first) {
        #pragma unroll
        for (int c = 0; c < KC; c++) { lmf[c] = -4.f; lmr[c] = -4.f; }
    } else {
        const float4* pf = reinterpret_cast<const float4*>(g_lm + (size_t)i * KC);
        const float4* pr = reinterpret_cast<const float4*>(g_lm + (size_t)er * KC);
        #pragma unroll
        for (int q = 0; q < 4; q++) {
            float4 v = pf[q];
            lmf[4*q+0] = v.x; lmf[4*q+1] = v.y; lmf[4*q+2] = v.z; lmf[4*q+3] = v.w;
            float4 w = pr[q];
            lmr[4*q+0] = w.x; lmr[4*q+1] = w.y; lmr[4*q+2] = w.z; lmr[4*q+3] = w.w;
        }
    }

    // message i: src s -> dst d; leave-one-out excludes reverse message lmr
    do_msg(Sin + (size_t)s * KC, lmr, g_lm + (size_t)i * KC,
           Snext + (size_t)d * KC, fast, off, s_a, s_psi);
    // message er (= reverse): src d -> dst s; excludes lmf
    do_msg(Sin + (size_t)d * KC, lmf, g_lm + (size_t)er * KC,
           Snext + (size_t)s * KC, fast, off, s_a, s_psi);
}

// beliefs: out = normalize(max(2^S, EPS))   (S already includes log2 prior)
__global__ void belief_kernel(int which, float* __restrict__ out, int n) {
    int i = blockIdx.x * blockDim.x + threadIdx.x;
    if (i >= n) return;
    const float* S = which ? g_SB : g_SA;
    const float4* pp = reinterpret_cast<const float4*>(S + (size_t)i * KC);
    float b[KC];
    float Z = 0.f;
    #pragma unroll
    for (int q = 0; q < 4; q++) {
        float4 v = pp[q];
        float x0 = fmaxf(ex2f(v.x), BP_EPS);
        float x1 = fmaxf(ex2f(v.y), BP_EPS);
        float x2 = fmaxf(ex2f(v.z), BP_EPS);
        float x3 = fmaxf(ex2f(v.w), BP_EPS);
        b[4*q+0] = x0; b[4*q+1] = x1; b[4*q+2] = x2; b[4*q+3] = x3;
        Z += x0 + x1 + x2 + x3;
    }
    float r = 1.f / Z;
    float4* po = reinterpret_cast<float4*>(out + (size_t)i * KC);
    #pragma unroll
    for (int q = 0; q < 4; q++) {
        float4 v;
        v.x = b[4*q+0] * r; v.y = b[4*q+1] * r; v.z = b[4*q+2] * r; v.w = b[4*q+3] * r;
        po[q] = v;
    }
}

extern "C" void kernel_launch(void* const* d_in, const int* in_sizes, int n_in,
                              void* d_out, int out_size) {
    const float* prior  = (const float*)d_in[0];
    const float* logpsi = (const float*)d_in[1];
    const int*   src    = (const int*)d_in[2];
    const int*   dst    = (const int*)d_in[3];
    const int*   rev    = (const int*)d_in[4];
    float* out = (float*)d_out;

    int n16 = in_sizes[0];      // n * 16
    int n   = n16 / KC;
    int e2  = in_sizes[2];      // directed edges
    int E   = e2 / 2;           // undirected pairs

    int gb_n16 = (n16 + 255) / 256;
    int gb_e2  = (e2 + 255) / 256;
    int gb_E   = (E + 255) / 256;
    int gb_n   = (n + 255) / 256;

    prep_psi_kernel<<<1, 256>>>(logpsi);

    // S_A = log2(prior) + deg_in * log2(1/16);  S_B = log2(prior)
    init_S_kernel<<<gb_n16, 256>>>(prior, 0, n16);
    acc_uniform_kernel<<<gb_e2, 256>>>(dst, 0, e2);
    init_S_kernel<<<gb_n16, 256>>>(prior, 1, n16);

    // iteration 1 (messages uniform -> skip lm read): A -> B
    update_kernel<<<gb_E, 256>>>(src, dst, rev, 1, E, 1);
    // iteration 2: B -> A
    init_S_kernel<<<gb_n16, 256>>>(prior, 0, n16);
    update_kernel<<<gb_E, 256>>>(src, dst, rev, 0, E, 0);
    // iteration 3: A -> B
    init_S_kernel<<<gb_n16, 256>>>(prior, 1, n16);
    update_kernel<<<gb_E, 256>>>(src, dst, rev, 1, E, 0);
    // iteration 4: B -> A
    init_S_kernel<<<gb_n16, 256>>>(prior, 0, n16);
    update_kernel<<<gb_E, 256>>>(src, dst, rev, 0, E, 0);

    belief_kernel<<<gb_n, 256>>>(0, out, n);
}